// round 11
// baseline (speedup 1.0000x reference)
#include <cuda_runtime.h>
#include <cuda_fp16.h>
#include <cstdint>

#define NROWS 100000
#define NPAD  100096          // 391 * 256 = 782 * 128
#define DIM 256
#define EPS 1e-6f
#define KV_SCALE_INV 256.0f   // KVh = KV / 256

#define SA 40                 // A-tile row stride (halves)
#define SB 136                // B/K/V-tile row stride (halves)
#define ABYTES_F (256 * SA * 2)   // fat A tile: 256 rows x 32 k
#define BBYTES   (32 * SB * 2)
#define STAGES 3
#define NTHRF 256             // fat CTA: 8 warps, 4x2 grid of 64x64 tiles
#define NTHRK 128             // kv CTA: 4 warps, 2x2 grid of 64x64 tiles

#define QKV_SMEM (STAGES * (ABYTES_F + BBYTES))   // 87552
#define OUT_SMEM (STAGES * (ABYTES_F + BBYTES))
#define KV_SMEM  (STAGES * 2 * BBYTES)            // 52224

#define KV_NCHUNK 125
#define KV_TILES 25           // 25*32 = 800 rows/chunk; 125*800 = 100000 exactly

// Scratch (allocation-guard-safe __device__ globals)
__device__ __half g_xh[NPAD * DIM];      // x as fp16 (pad rows stay zero)
__device__ __half g_Q[NPAD * DIM];
__device__ __half g_K[NPAD * DIM];
__device__ __half g_V[NPAD * DIM];
__device__ __half g_Wh[3 * DIM * DIM];   // [z][k][n] fp16
__device__ float  g_KV[DIM * DIM];
__device__ __half g_KVh[DIM * DIM];      // KV / 256 as fp16, [d][e]
__device__ float  g_ksum[DIM];
__device__ float  g_norm[NROWS];

// ---------------------------------------------------------------------------
// PTX helpers
// ---------------------------------------------------------------------------
__device__ __forceinline__ uint32_t smem_u32(const void* p) {
    uint32_t a;
    asm("{ .reg .u64 t; cvta.to.shared.u64 t, %1; cvt.u32.u64 %0, t; }" : "=r"(a) : "l"(p));
    return a;
}

__device__ __forceinline__ void cp16(uint32_t dst, const void* src) {
    asm volatile("cp.async.cg.shared.global [%0], [%1], 16;" :: "r"(dst), "l"(src));
}
#define CP_COMMIT() asm volatile("cp.async.commit_group;" ::: "memory")
#define CP_WAIT(n)  asm volatile("cp.async.wait_group %0;" :: "n"(n) : "memory")

#define LDSM_X4(r, addr) \
    asm volatile("ldmatrix.sync.aligned.m8n8.x4.shared.b16 {%0,%1,%2,%3}, [%4];" \
                 : "=r"((r)[0]), "=r"((r)[1]), "=r"((r)[2]), "=r"((r)[3]) : "r"(addr))
#define LDSM_X4T(r, addr) \
    asm volatile("ldmatrix.sync.aligned.m8n8.x4.trans.shared.b16 {%0,%1,%2,%3}, [%4];" \
                 : "=r"((r)[0]), "=r"((r)[1]), "=r"((r)[2]), "=r"((r)[3]) : "r"(addr))

__device__ __forceinline__ void mma_fp16(float c[4], const uint32_t a[4],
                                         uint32_t b0, uint32_t b1) {
    asm volatile(
        "mma.sync.aligned.m16n8k16.row.col.f32.f16.f16.f32 "
        "{%0,%1,%2,%3},{%4,%5,%6,%7},{%8,%9},{%0,%1,%2,%3};\n"
        : "+f"(c[0]), "+f"(c[1]), "+f"(c[2]), "+f"(c[3])
        : "r"(a[0]), "r"(a[1]), "r"(a[2]), "r"(a[3]), "r"(b0), "r"(b1));
}

__device__ __forceinline__ uint32_t pack_h2(float a, float b) {
    __half2 h = __floats2half2_rn(a, b);
    return *reinterpret_cast<uint32_t*>(&h);
}

// ---------------------------------------------------------------------------
// prep: x -> fp16 (g_xh) and W -> fp16 (g_Wh), one launch
// ---------------------------------------------------------------------------
__global__ void prep_kernel(const float* __restrict__ x,
                            const float* __restrict__ Wq,
                            const float* __restrict__ Wk,
                            const float* __restrict__ Wv) {
    const long id = (long)blockIdx.x * 256 + threadIdx.x;
    const long xgroups = (long)NROWS * DIM / 8;
    const float* src;
    __half* dst;
    long off;
    if (id < xgroups) {
        src = x; dst = g_xh; off = id * 8;
    } else {
        const long wi = id - xgroups;            // 0..24575
        const int z = (int)(wi >> 13);           // 8192 groups per matrix
        src = (z == 0) ? Wq : (z == 1) ? Wk : Wv;
        dst = g_Wh + z * DIM * DIM;
        off = (wi & 8191) * 8;
    }
    const float4 f0 = *(const float4*)&src[off];
    const float4 f1 = *(const float4*)&src[off + 4];
    uint4 u;
    u.x = pack_h2(f0.x, f0.y); u.y = pack_h2(f0.z, f0.w);
    u.z = pack_h2(f1.x, f1.y); u.w = pack_h2(f1.z, f1.w);
    *(uint4*)&dst[off] = u;
}

// init: zero accumulators (every replay)
__global__ void init_kernel() {
    int t = blockIdx.x * blockDim.x + threadIdx.x;
    if (t < DIM * DIM) g_KV[t] = 0.0f;
    if (t < DIM)       g_ksum[t] = 0.0f;
}

// ---------------------------------------------------------------------------
// qkv (fat CTA): 256 thr, 256x128 tile, 4x2 warps of 64x64.  ksum fused (z==1)
// grid (6, 391): x = z*2 + colhalf fastest -> x-tile L2 reuse
// ---------------------------------------------------------------------------
__global__ __launch_bounds__(NTHRF, 1) void qkv_kernel(
    const float* __restrict__ bq, const float* __restrict__ bk,
    const float* __restrict__ bv)
{
    extern __shared__ char dsm[];
    __shared__ float colsum[128];

    const int t = threadIdx.x;
    const int l = t & 31, w = t >> 5;
    const int wm = w >> 1, wn = w & 1;      // 4x2 warps, 64x64 tiles

    const int zy = blockIdx.x;
    const int z = zy >> 1;
    const int col0 = (zy & 1) * 128;
    const int row0 = blockIdx.y * 256;

    const __half* Wh = g_Wh + z * DIM * DIM;
    const float* bias = (z == 0) ? bq : (z == 1) ? bk : bv;
    __half* C = (z == 0) ? g_Q : (z == 1) ? g_K : g_V;
    const bool relu = (z < 2);

    if (t < 128) colsum[t] = 0.0f;

    const uint32_t as_base = smem_u32(dsm);
    const uint32_t bs_base = as_base + STAGES * ABYTES_F;
    const int aoff = (l & 15) * SA + (l >> 4) * 8;
    const int boff = ((l & 7) + ((l >> 3) & 1) * 8) * SB + (l >> 4) * 8;

    float c[4][8][4];
#pragma unroll
    for (int mt = 0; mt < 4; mt++)
#pragma unroll
        for (int nt = 0; nt < 8; nt++)
#pragma unroll
            for (int r = 0; r < 4; r++) c[mt][nt][r] = 0.0f;

    auto cp = [&](int kt) {
        const int s = kt % STAGES;
        const uint32_t da = as_base + s * ABYTES_F;
#pragma unroll
        for (int i = 0; i < 4; i++) {
            const int id = t + i * NTHRF;      // 0..1023
            const int row = id >> 2, cg = id & 3;
            cp16(da + (row * SA + cg * 8) * 2,
                 &g_xh[(row0 + row) * DIM + kt * 32 + cg * 8]);
        }
        const uint32_t db = bs_base + s * BBYTES;
#pragma unroll
        for (int i = 0; i < 2; i++) {
            const int id = t + i * NTHRF;      // 0..511
            const int row = id >> 4, cg = id & 15;
            cp16(db + (row * SB + cg * 8) * 2,
                 &Wh[(kt * 32 + row) * DIM + col0 + cg * 8]);
        }
        CP_COMMIT();
    };
    auto compute = [&](int s) {
        const uint32_t ab = as_base + s * ABYTES_F;
        const uint32_t bb = bs_base + s * BBYTES;
#pragma unroll
        for (int ks = 0; ks < 2; ks++) {
            uint32_t a[4][4];
#pragma unroll
            for (int mt = 0; mt < 4; mt++)
                LDSM_X4(a[mt], ab + 2 * ((wm * 64 + mt * 16) * SA + ks * 16 + aoff));
            uint32_t b[4][4];
#pragma unroll
            for (int nt2 = 0; nt2 < 4; nt2++)
                LDSM_X4T(b[nt2], bb + 2 * (ks * 16 * SB + wn * 64 + nt2 * 16 + boff));
#pragma unroll
            for (int mt = 0; mt < 4; mt++)
#pragma unroll
                for (int nt = 0; nt < 8; nt++) {
                    const int nt2 = nt >> 1, i0 = (nt & 1) * 2;
                    mma_fp16(c[mt][nt], a[mt], b[nt2][i0], b[nt2][i0 + 1]);
                }
        }
    };

    cp(0); cp(1);
#pragma unroll 1
    for (int kt = 0; kt < 8; kt++) {
        if (kt + 2 < 8) cp(kt + 2);
        if (kt < 6) CP_WAIT(2); else if (kt == 6) CP_WAIT(1); else CP_WAIT(0);
        __syncthreads();
        compute(kt % STAGES);
        __syncthreads();
    }

    // epilogue: bias (+relu), fp16 stores, ksum partials (z==1)
#pragma unroll
    for (int mt = 0; mt < 4; mt++) {
        const int gr0 = row0 + wm * 64 + mt * 16 + (l >> 2);
        const int gr1 = gr0 + 8;
#pragma unroll
        for (int nt = 0; nt < 8; nt++) {
            const int col = col0 + wn * 64 + nt * 8 + (l & 3) * 2;
            const float bb0 = bias[col], bb1 = bias[col + 1];
            float v0 = c[mt][nt][0] + bb0, v1 = c[mt][nt][1] + bb1;
            float v2 = c[mt][nt][2] + bb0, v3 = c[mt][nt][3] + bb1;
            if (relu) {
                v0 = fmaxf(v0, 0.f); v1 = fmaxf(v1, 0.f);
                v2 = fmaxf(v2, 0.f); v3 = fmaxf(v3, 0.f);
            }
            *(__half2*)&C[gr0 * DIM + col] = __floats2half2_rn(v0, v1);   // NPAD in-bounds
            *(__half2*)&C[gr1 * DIM + col] = __floats2half2_rn(v2, v3);
            if (z == 1) {
                float s0 = (gr0 < NROWS ? v0 : 0.f) + (gr1 < NROWS ? v2 : 0.f);
                float s1 = (gr0 < NROWS ? v1 : 0.f) + (gr1 < NROWS ? v3 : 0.f);
                atomicAdd(&colsum[col - col0], s0);
                atomicAdd(&colsum[col - col0 + 1], s1);
            }
        }
    }
    if (z == 1) {
        __syncthreads();
        if (t < 128) atomicAdd(&g_ksum[col0 + t], colsum[t]);
    }
}

// ---------------------------------------------------------------------------
// kv: KV[d][e] += sum_n K[n][d] * V[n][e]  (R10 config: 128 thr, 64x64 tiles)
// grid (4, 125): x fastest -> chunk K/V tiles reused via L2
// ---------------------------------------------------------------------------
__global__ __launch_bounds__(NTHRK, 2) void kv_kernel() {
    extern __shared__ char dsm[];

    const int t = threadIdx.x;
    const int l = t & 31, w = t >> 5;
    const int wm = w >> 1, wn = w & 1;

    const int d0 = (blockIdx.x & 1) * 128;
    const int e0 = (blockIdx.x >> 1) * 128;
    const int n0 = blockIdx.y * (KV_TILES * 32);

    const uint32_t kb_base = smem_u32(dsm);
    const uint32_t vb_base = kb_base + STAGES * BBYTES;
    const int kaoff = ((l & 7) + (l >> 4) * 8) * SB + ((l >> 3) & 1) * 8;
    const int boff  = ((l & 7) + ((l >> 3) & 1) * 8) * SB + (l >> 4) * 8;

    float c[4][8][4];
#pragma unroll
    for (int mt = 0; mt < 4; mt++)
#pragma unroll
        for (int nt = 0; nt < 8; nt++)
#pragma unroll
            for (int r = 0; r < 4; r++) c[mt][nt][r] = 0.0f;

    auto cp = [&](int kt) {
        const int s = kt % STAGES;
        const uint32_t kd = kb_base + s * BBYTES;
        const uint32_t vd = vb_base + s * BBYTES;
        const int gn0 = n0 + kt * 32;
#pragma unroll
        for (int i = 0; i < 4; i++) {
            const int id = t + i * NTHRK;
            const int row = id >> 4, cg = id & 15;
            cp16(kd + (row * SB + cg * 8) * 2, &g_K[(gn0 + row) * DIM + d0 + cg * 8]);
            cp16(vd + (row * SB + cg * 8) * 2, &g_V[(gn0 + row) * DIM + e0 + cg * 8]);
        }
        CP_COMMIT();
    };
    auto compute = [&](int s) {
        const uint32_t kb = kb_base + s * BBYTES;
        const uint32_t vb = vb_base + s * BBYTES;
#pragma unroll
        for (int ks = 0; ks < 2; ks++) {
            uint32_t a[4][4];
#pragma unroll
            for (int mt = 0; mt < 4; mt++)
                LDSM_X4T(a[mt], kb + 2 * (ks * 16 * SB + wm * 64 + mt * 16 + kaoff));
            uint32_t b[4][4];
#pragma unroll
            for (int nt2 = 0; nt2 < 4; nt2++)
                LDSM_X4T(b[nt2], vb + 2 * (ks * 16 * SB + wn * 64 + nt2 * 16 + boff));
#pragma unroll
            for (int mt = 0; mt < 4; mt++)
#pragma unroll
                for (int nt = 0; nt < 8; nt++) {
                    const int nt2 = nt >> 1, i0 = (nt & 1) * 2;
                    mma_fp16(c[mt][nt], a[mt], b[nt2][i0], b[nt2][i0 + 1]);
                }
        }
    };

    cp(0); cp(1);
#pragma unroll 1
    for (int kt = 0; kt < KV_TILES; kt++) {
        if (kt + 2 < KV_TILES) cp(kt + 2);
        if (kt < KV_TILES - 2) CP_WAIT(2);
        else if (kt == KV_TILES - 2) CP_WAIT(1);
        else CP_WAIT(0);
        __syncthreads();
        compute(kt % STAGES);
        __syncthreads();
    }

#pragma unroll
    for (int mt = 0; mt < 4; mt++) {
        const int dr0 = d0 + wm * 64 + mt * 16 + (l >> 2);
#pragma unroll
        for (int nt = 0; nt < 8; nt++) {
            const int ec = e0 + wn * 64 + nt * 8 + (l & 3) * 2;
            atomicAdd(&g_KV[dr0 * DIM + ec],           c[mt][nt][0]);
            atomicAdd(&g_KV[dr0 * DIM + ec + 1],       c[mt][nt][1]);
            atomicAdd(&g_KV[(dr0 + 8) * DIM + ec],     c[mt][nt][2]);
            atomicAdd(&g_KV[(dr0 + 8) * DIM + ec + 1], c[mt][nt][3]);
        }
    }
}

// ---------------------------------------------------------------------------
// norm (+kvh fused): g_norm[n] = dot(Q[n], ksum) + EPS; blocks 0..63 also
// convert KV -> KVh.
// ---------------------------------------------------------------------------
__global__ void norm_kernel() {
    if (blockIdx.x < 64) {
        const int i = (blockIdx.x * 256 + threadIdx.x) * 4;
        const float4 f = *(const float4*)&g_KV[i];
        const float s = 1.0f / KV_SCALE_INV;
        uint2 u;
        u.x = pack_h2(f.x * s, f.y * s);
        u.y = pack_h2(f.z * s, f.w * s);
        *(uint2*)&g_KVh[i] = u;
    }

    __shared__ float ks[DIM];
    const int t = threadIdx.x;
    if (t < DIM) ks[t] = g_ksum[t];
    __syncthreads();

    const int lane = t & 31;
    const int gw = (blockIdx.x * blockDim.x + t) >> 5;
    const int nw = (gridDim.x * blockDim.x) >> 5;
    for (int p = gw; p < NROWS / 2; p += nw) {
        const int r0 = p * 2, r1 = p * 2 + 1;
        const uint4 raw0 = *(const uint4*)&g_Q[r0 * DIM + lane * 8];
        const uint4 raw1 = *(const uint4*)&g_Q[r1 * DIM + lane * 8];
        const __half2* h0 = (const __half2*)&raw0;
        const __half2* h1 = (const __half2*)&raw1;
        float s0 = 0.0f, s1 = 0.0f;
#pragma unroll
        for (int i = 0; i < 4; i++) {
            const float k0 = ks[lane * 8 + i * 2], k1 = ks[lane * 8 + i * 2 + 1];
            float2 f0 = __half22float2(h0[i]);
            float2 f1 = __half22float2(h1[i]);
            s0 += f0.x * k0 + f0.y * k1;
            s1 += f1.x * k0 + f1.y * k1;
        }
#pragma unroll
        for (int o = 16; o; o >>= 1) {
            s0 += __shfl_xor_sync(0xffffffffu, s0, o);
            s1 += __shfl_xor_sync(0xffffffffu, s1, o);
        }
        if (lane == 0) { g_norm[r0] = s0 + EPS; g_norm[r1] = s1 + EPS; }
    }
}

// ---------------------------------------------------------------------------
// out (fat CTA): out = (Q @ KVh) * 256 / norm   grid (2, 391)
// ---------------------------------------------------------------------------
__global__ __launch_bounds__(NTHRF, 1) void out_kernel(float* __restrict__ out) {
    extern __shared__ char dsm[];

    const int t = threadIdx.x;
    const int l = t & 31, w = t >> 5;
    const int wm = w >> 1, wn = w & 1;

    const int col0 = blockIdx.x * 128;
    const int row0 = blockIdx.y * 256;

    const uint32_t as_base = smem_u32(dsm);
    const uint32_t bs_base = as_base + STAGES * ABYTES_F;
    const int aoff = (l & 15) * SA + (l >> 4) * 8;
    const int boff = ((l & 7) + ((l >> 3) & 1) * 8) * SB + (l >> 4) * 8;

    float c[4][8][4];
#pragma unroll
    for (int mt = 0; mt < 4; mt++)
#pragma unroll
        for (int nt = 0; nt < 8; nt++)
#pragma unroll
            for (int r = 0; r < 4; r++) c[mt][nt][r] = 0.0f;

    auto cp = [&](int kt) {
        const int s = kt % STAGES;
        const uint32_t da = as_base + s * ABYTES_F;
#pragma unroll
        for (int i = 0; i < 4; i++) {
            const int id = t + i * NTHRF;
            const int row = id >> 2, cg = id & 3;
            cp16(da + (row * SA + cg * 8) * 2,
                 &g_Q[(row0 + row) * DIM + kt * 32 + cg * 8]);
        }
        const uint32_t db = bs_base + s * BBYTES;
#pragma unroll
        for (int i = 0; i < 2; i++) {
            const int id = t + i * NTHRF;
            const int row = id >> 4, cg = id & 15;
            cp16(db + (row * SB + cg * 8) * 2,
                 &g_KVh[(kt * 32 + row) * DIM + col0 + cg * 8]);
        }
        CP_COMMIT();
    };
    auto compute = [&](int s) {
        const uint32_t ab = as_base + s * ABYTES_F;
        const uint32_t bb = bs_base + s * BBYTES;
#pragma unroll
        for (int ks = 0; ks < 2; ks++) {
            uint32_t a[4][4];
#pragma unroll
            for (int mt = 0; mt < 4; mt++)
                LDSM_X4(a[mt], ab + 2 * ((wm * 64 + mt * 16) * SA + ks * 16 + aoff));
            uint32_t b[4][4];
#pragma unroll
            for (int nt2 = 0; nt2 < 4; nt2++)
                LDSM_X4T(b[nt2], bb + 2 * (ks * 16 * SB + wn * 64 + nt2 * 16 + boff));
#pragma unroll
            for (int mt = 0; mt < 4; mt++)
#pragma unroll
                for (int nt = 0; nt < 8; nt++) {
                    const int nt2 = nt >> 1, i0 = (nt & 1) * 2;
                    mma_fp16(c[mt][nt], a[mt], b[nt2][i0], b[nt2][i0 + 1]);
                }
        }
    };

    cp(0); cp(1);
#pragma unroll 1
    for (int kt = 0; kt < 8; kt++) {
        if (kt + 2 < 8) cp(kt + 2);
        if (kt < 6) CP_WAIT(2); else if (kt == 6) CP_WAIT(1); else CP_WAIT(0);
        __syncthreads();
        compute(kt % STAGES);
        __syncthreads();
    }

#pragma unroll
    for (int mt = 0; mt < 4; mt++) {
        const int gr0 = row0 + wm * 64 + mt * 16 + (l >> 2);
        const int gr1 = gr0 + 8;
        const float inv0 = (gr0 < NROWS) ? KV_SCALE_INV / g_norm[gr0] : 0.0f;
        const float inv1 = (gr1 < NROWS) ? KV_SCALE_INV / g_norm[gr1] : 0.0f;
#pragma unroll
        for (int nt = 0; nt < 8; nt++) {
            const int col = col0 + wn * 64 + nt * 8 + (l & 3) * 2;
            if (gr0 < NROWS)
                *(float2*)&out[gr0 * DIM + col] =
                    make_float2(c[mt][nt][0] * inv0, c[mt][nt][1] * inv0);
            if (gr1 < NROWS)
                *(float2*)&out[gr1 * DIM + col] =
                    make_float2(c[mt][nt][2] * inv1, c[mt][nt][3] * inv1);
        }
    }
}

// ---------------------------------------------------------------------------
extern "C" void kernel_launch(void* const* d_in, const int* in_sizes, int n_in,
                              void* d_out, int out_size) {
    const float* x  = (const float*)d_in[0];
    const float* Wq = (const float*)d_in[1];
    const float* bq = (const float*)d_in[2];
    const float* Wk = (const float*)d_in[3];
    const float* bk = (const float*)d_in[4];
    const float* Wv = (const float*)d_in[5];
    const float* bv = (const float*)d_in[6];
    float* out = (float*)d_out;

    cudaFuncSetAttribute(qkv_kernel, cudaFuncAttributeMaxDynamicSharedMemorySize, QKV_SMEM);
    cudaFuncSetAttribute(kv_kernel,  cudaFuncAttributeMaxDynamicSharedMemorySize, KV_SMEM);
    cudaFuncSetAttribute(out_kernel, cudaFuncAttributeMaxDynamicSharedMemorySize, OUT_SMEM);

    const int rowTilesF = NPAD / 256;   // 391

    prep_kernel<<<12596, 256>>>(x, Wq, Wk, Wv);
    init_kernel<<<(DIM * DIM + 255) / 256, 256>>>();
    qkv_kernel<<<dim3(6, rowTilesF), NTHRF, QKV_SMEM>>>(bq, bk, bv);
    kv_kernel<<<dim3(4, KV_NCHUNK), NTHRK, KV_SMEM>>>();
    norm_kernel<<<1184, 256>>>();
    out_kernel<<<dim3(2, rowTilesF), NTHRF, OUT_SMEM>>>(out);
}

// round 15
// speedup vs baseline: 1.2990x; 1.2990x over previous
#include <cuda_runtime.h>
#include <cuda_fp16.h>
#include <cstdint>

#define NROWS 100000
#define NPAD  100096          // 782 * 128
#define DIM 256
#define EPS 1e-6f
#define KV_SCALE_INV 256.0f   // KVh = KV / 256

#define SA 40                 // A-tile row stride (halves), 128 rows x 32 k
#define SB 136                // B/K/V-tile row stride (halves), 32 rows x 128 cols
#define ABYTES (128 * SA * 2)
#define BBYTES (32 * SB * 2)
#define STAGES 4              // 4 stages, prefetch distance 2, ONE barrier/tile

#define QKV_SMEM (STAGES * (ABYTES + BBYTES))   // 75776
#define OUT_SMEM (STAGES * (ABYTES + BBYTES))
#define KV_SMEM  (STAGES * 2 * BBYTES)          // 69632

#define KV_NCHUNK 125
#define KV_TILES 25           // 25*32 = 800 rows/chunk; 125*800 = 100000 exactly

// Scratch (allocation-guard-safe __device__ globals)
__device__ __half g_xh[NPAD * DIM];      // x as fp16 (pad rows stay zero)
__device__ __half g_Q[NPAD * DIM];
__device__ __half g_K[NPAD * DIM];
__device__ __half g_V[NPAD * DIM];
__device__ __half g_Wh[3 * DIM * DIM];   // [z][k][n] fp16
__device__ float  g_KV[DIM * DIM];
__device__ __half g_KVh[DIM * DIM];      // KV / 256 as fp16, [d][e]
__device__ float  g_ksum[DIM];
__device__ float  g_norm[NROWS];

// ---------------------------------------------------------------------------
// PTX helpers
// ---------------------------------------------------------------------------
__device__ __forceinline__ uint32_t smem_u32(const void* p) {
    uint32_t a;
    asm("{ .reg .u64 t; cvta.to.shared.u64 t, %1; cvt.u32.u64 %0, t; }" : "=r"(a) : "l"(p));
    return a;
}

__device__ __forceinline__ void cp16(uint32_t dst, const void* src) {
    asm volatile("cp.async.cg.shared.global [%0], [%1], 16;" :: "r"(dst), "l"(src));
}
#define CP_COMMIT() asm volatile("cp.async.commit_group;" ::: "memory")
#define CP_WAIT(n)  asm volatile("cp.async.wait_group %0;" :: "n"(n) : "memory")

#define LDSM_X4(r, addr) \
    asm volatile("ldmatrix.sync.aligned.m8n8.x4.shared.b16 {%0,%1,%2,%3}, [%4];" \
                 : "=r"((r)[0]), "=r"((r)[1]), "=r"((r)[2]), "=r"((r)[3]) : "r"(addr))
#define LDSM_X4T(r, addr) \
    asm volatile("ldmatrix.sync.aligned.m8n8.x4.trans.shared.b16 {%0,%1,%2,%3}, [%4];" \
                 : "=r"((r)[0]), "=r"((r)[1]), "=r"((r)[2]), "=r"((r)[3]) : "r"(addr))

__device__ __forceinline__ void mma_fp16(float c[4], const uint32_t a[4],
                                         uint32_t b0, uint32_t b1) {
    asm volatile(
        "mma.sync.aligned.m16n8k16.row.col.f32.f16.f16.f32 "
        "{%0,%1,%2,%3},{%4,%5,%6,%7},{%8,%9},{%0,%1,%2,%3};\n"
        : "+f"(c[0]), "+f"(c[1]), "+f"(c[2]), "+f"(c[3])
        : "r"(a[0]), "r"(a[1]), "r"(a[2]), "r"(a[3]), "r"(b0), "r"(b1));
}

__device__ __forceinline__ uint32_t pack_h2(float a, float b) {
    __half2 h = __floats2half2_rn(a, b);
    return *reinterpret_cast<uint32_t*>(&h);
}

// ---------------------------------------------------------------------------
// prep: x -> fp16 (g_xh) and W -> fp16 (g_Wh), one launch
// ---------------------------------------------------------------------------
__global__ void prep_kernel(const float* __restrict__ x,
                            const float* __restrict__ Wq,
                            const float* __restrict__ Wk,
                            const float* __restrict__ Wv) {
    const long id = (long)blockIdx.x * 256 + threadIdx.x;
    const long xgroups = (long)NROWS * DIM / 8;
    const float* src;
    __half* dst;
    long off;
    if (id < xgroups) {
        src = x; dst = g_xh; off = id * 8;
    } else {
        const long wi = id - xgroups;            // 0..24575
        const int z = (int)(wi >> 13);           // 8192 groups per matrix
        src = (z == 0) ? Wq : (z == 1) ? Wk : Wv;
        dst = g_Wh + z * DIM * DIM;
        off = (wi & 8191) * 8;
    }
    const float4 f0 = *(const float4*)&src[off];
    const float4 f1 = *(const float4*)&src[off + 4];
    uint4 u;
    u.x = pack_h2(f0.x, f0.y); u.y = pack_h2(f0.z, f0.w);
    u.z = pack_h2(f1.x, f1.y); u.w = pack_h2(f1.z, f1.w);
    *(uint4*)&dst[off] = u;
}

// init: zero accumulators (every replay)
__global__ void init_kernel() {
    int t = blockIdx.x * blockDim.x + threadIdx.x;
    if (t < DIM * DIM) g_KV[t] = 0.0f;
    if (t < DIM)       g_ksum[t] = 0.0f;
}

// ---------------------------------------------------------------------------
// qkv: 256 thr, 128x128 tile, 4x2 warps of 32x64 (R9 shape). ksum fused (z==1)
// grid (6, 782). 4-stage single-barrier pipeline.
// ---------------------------------------------------------------------------
__global__ __launch_bounds__(256, 2) void qkv_kernel(
    const float* __restrict__ bq, const float* __restrict__ bk,
    const float* __restrict__ bv)
{
    extern __shared__ char dsm[];
    __shared__ float colsum[128];

    const int t = threadIdx.x;
    const int l = t & 31, w = t >> 5;
    const int wm = w >> 1, wn = w & 1;      // 4x2 warps, 32x64 tiles

    const int zy = blockIdx.x;
    const int z = zy >> 1;
    const int col0 = (zy & 1) * 128;
    const int row0 = blockIdx.y * 128;

    const __half* Wh = g_Wh + z * DIM * DIM;
    const float* bias = (z == 0) ? bq : (z == 1) ? bk : bv;
    __half* C = (z == 0) ? g_Q : (z == 1) ? g_K : g_V;
    const bool relu = (z < 2);

    if (t < 128) colsum[t] = 0.0f;

    const uint32_t as_base = smem_u32(dsm);
    const uint32_t bs_base = as_base + STAGES * ABYTES;
    const int aoff = (l & 15) * SA + (l >> 4) * 8;
    const int boff = ((l & 7) + ((l >> 3) & 1) * 8) * SB + (l >> 4) * 8;

    float c[2][8][4];
#pragma unroll
    for (int mt = 0; mt < 2; mt++)
#pragma unroll
        for (int nt = 0; nt < 8; nt++)
#pragma unroll
            for (int r = 0; r < 4; r++) c[mt][nt][r] = 0.0f;

    auto cp = [&](int kt) {
        const int s = kt % STAGES;
        const uint32_t da = as_base + s * ABYTES;
#pragma unroll
        for (int i = 0; i < 2; i++) {
            const int id = t + i * 256;
            const int row = id >> 2, cg = id & 3;
            cp16(da + (row * SA + cg * 8) * 2,
                 &g_xh[(row0 + row) * DIM + kt * 32 + cg * 8]);
        }
        const uint32_t db = bs_base + s * BBYTES;
#pragma unroll
        for (int i = 0; i < 2; i++) {
            const int id = t + i * 256;
            const int row = id >> 4, cg = id & 15;
            cp16(db + (row * SB + cg * 8) * 2,
                 &Wh[(kt * 32 + row) * DIM + col0 + cg * 8]);
        }
        CP_COMMIT();
    };
    auto compute = [&](int s) {
        const uint32_t ab = as_base + s * ABYTES;
        const uint32_t bb = bs_base + s * BBYTES;
#pragma unroll
        for (int ks = 0; ks < 2; ks++) {
            uint32_t a[2][4];
#pragma unroll
            for (int mt = 0; mt < 2; mt++)
                LDSM_X4(a[mt], ab + 2 * ((wm * 32 + mt * 16) * SA + ks * 16 + aoff));
            uint32_t b[4][4];
#pragma unroll
            for (int nt2 = 0; nt2 < 4; nt2++)
                LDSM_X4T(b[nt2], bb + 2 * (ks * 16 * SB + wn * 64 + nt2 * 16 + boff));
#pragma unroll
            for (int mt = 0; mt < 2; mt++)
#pragma unroll
                for (int nt = 0; nt < 8; nt++) {
                    const int nt2 = nt >> 1, i0 = (nt & 1) * 2;
                    mma_fp16(c[mt][nt], a[mt], b[nt2][i0], b[nt2][i0 + 1]);
                }
        }
    };

    cp(0); cp(1);
#pragma unroll 1
    for (int kt = 0; kt < 8; kt++) {
        if (kt + 2 < 8) cp(kt + 2);
        if (kt < 6) CP_WAIT(2); else if (kt == 6) CP_WAIT(1); else CP_WAIT(0);
        __syncthreads();
        compute(kt % STAGES);
    }

    // epilogue: bias (+relu), fp16 stores, ksum partials (z==1)
#pragma unroll
    for (int mt = 0; mt < 2; mt++) {
        const int gr0 = row0 + wm * 32 + mt * 16 + (l >> 2);
        const int gr1 = gr0 + 8;
#pragma unroll
        for (int nt = 0; nt < 8; nt++) {
            const int col = col0 + wn * 64 + nt * 8 + (l & 3) * 2;
            const float bb0 = bias[col], bb1 = bias[col + 1];
            float v0 = c[mt][nt][0] + bb0, v1 = c[mt][nt][1] + bb1;
            float v2 = c[mt][nt][2] + bb0, v3 = c[mt][nt][3] + bb1;
            if (relu) {
                v0 = fmaxf(v0, 0.f); v1 = fmaxf(v1, 0.f);
                v2 = fmaxf(v2, 0.f); v3 = fmaxf(v3, 0.f);
            }
            *(__half2*)&C[gr0 * DIM + col] = __floats2half2_rn(v0, v1);
            *(__half2*)&C[gr1 * DIM + col] = __floats2half2_rn(v2, v3);
            if (z == 1) {
                float s0 = (gr0 < NROWS ? v0 : 0.f) + (gr1 < NROWS ? v2 : 0.f);
                float s1 = (gr0 < NROWS ? v1 : 0.f) + (gr1 < NROWS ? v3 : 0.f);
                atomicAdd(&colsum[col - col0], s0);
                atomicAdd(&colsum[col - col0 + 1], s1);
            }
        }
    }
    if (z == 1) {
        __syncthreads();
        if (t < 128) atomicAdd(&g_ksum[col0 + t], colsum[t]);
    }
}

// ---------------------------------------------------------------------------
// kv: 128 thr, 2x2 warps of 64x64 (R10 shape). 4-stage single-barrier.
// grid (4, 125): x fastest -> chunk K/V tiles reused via L2
// ---------------------------------------------------------------------------
__global__ __launch_bounds__(128, 2) void kv_kernel() {
    extern __shared__ char dsm[];

    const int t = threadIdx.x;
    const int l = t & 31, w = t >> 5;
    const int wm = w >> 1, wn = w & 1;

    const int d0 = (blockIdx.x & 1) * 128;
    const int e0 = (blockIdx.x >> 1) * 128;
    const int n0 = blockIdx.y * (KV_TILES * 32);

    const uint32_t kb_base = smem_u32(dsm);
    const uint32_t vb_base = kb_base + STAGES * BBYTES;
    const int kaoff = ((l & 7) + (l >> 4) * 8) * SB + ((l >> 3) & 1) * 8;
    const int boff  = ((l & 7) + ((l >> 3) & 1) * 8) * SB + (l >> 4) * 8;

    float c[4][8][4];
#pragma unroll
    for (int mt = 0; mt < 4; mt++)
#pragma unroll
        for (int nt = 0; nt < 8; nt++)
#pragma unroll
            for (int r = 0; r < 4; r++) c[mt][nt][r] = 0.0f;

    auto cp = [&](int kt) {
        const int s = kt % STAGES;
        const uint32_t kd = kb_base + s * BBYTES;
        const uint32_t vd = vb_base + s * BBYTES;
        const int gn0 = n0 + kt * 32;
#pragma unroll
        for (int i = 0; i < 4; i++) {
            const int id = t + i * 128;
            const int row = id >> 4, cg = id & 15;
            cp16(kd + (row * SB + cg * 8) * 2, &g_K[(gn0 + row) * DIM + d0 + cg * 8]);
            cp16(vd + (row * SB + cg * 8) * 2, &g_V[(gn0 + row) * DIM + e0 + cg * 8]);
        }
        CP_COMMIT();
    };
    auto compute = [&](int s) {
        const uint32_t kb = kb_base + s * BBYTES;
        const uint32_t vb = vb_base + s * BBYTES;
#pragma unroll
        for (int ks = 0; ks < 2; ks++) {
            uint32_t a[4][4];
#pragma unroll
            for (int mt = 0; mt < 4; mt++)
                LDSM_X4T(a[mt], kb + 2 * (ks * 16 * SB + wm * 64 + mt * 16 + kaoff));
            uint32_t b[4][4];
#pragma unroll
            for (int nt2 = 0; nt2 < 4; nt2++)
                LDSM_X4T(b[nt2], vb + 2 * (ks * 16 * SB + wn * 64 + nt2 * 16 + boff));
#pragma unroll
            for (int mt = 0; mt < 4; mt++)
#pragma unroll
                for (int nt = 0; nt < 8; nt++) {
                    const int nt2 = nt >> 1, i0 = (nt & 1) * 2;
                    mma_fp16(c[mt][nt], a[mt], b[nt2][i0], b[nt2][i0 + 1]);
                }
        }
    };

    cp(0); cp(1);
#pragma unroll 1
    for (int kt = 0; kt < KV_TILES; kt++) {
        if (kt + 2 < KV_TILES) cp(kt + 2);
        if (kt < KV_TILES - 2) CP_WAIT(2);
        else if (kt == KV_TILES - 2) CP_WAIT(1);
        else CP_WAIT(0);
        __syncthreads();
        compute(kt % STAGES);
    }

#pragma unroll
    for (int mt = 0; mt < 4; mt++) {
        const int dr0 = d0 + wm * 64 + mt * 16 + (l >> 2);
#pragma unroll
        for (int nt = 0; nt < 8; nt++) {
            const int ec = e0 + wn * 64 + nt * 8 + (l & 3) * 2;
            atomicAdd(&g_KV[dr0 * DIM + ec],           c[mt][nt][0]);
            atomicAdd(&g_KV[dr0 * DIM + ec + 1],       c[mt][nt][1]);
            atomicAdd(&g_KV[(dr0 + 8) * DIM + ec],     c[mt][nt][2]);
            atomicAdd(&g_KV[(dr0 + 8) * DIM + ec + 1], c[mt][nt][3]);
        }
    }
}

// ---------------------------------------------------------------------------
// norm (+kvh fused): g_norm[n] = dot(Q[n], ksum) + EPS; blocks 0..63 also
// convert KV -> KVh.
// ---------------------------------------------------------------------------
__global__ void norm_kernel() {
    if (blockIdx.x < 64) {
        const int i = (blockIdx.x * 256 + threadIdx.x) * 4;
        const float4 f = *(const float4*)&g_KV[i];
        const float s = 1.0f / KV_SCALE_INV;
        uint2 u;
        u.x = pack_h2(f.x * s, f.y * s);
        u.y = pack_h2(f.z * s, f.w * s);
        *(uint2*)&g_KVh[i] = u;
    }

    __shared__ float ks[DIM];
    const int t = threadIdx.x;
    if (t < DIM) ks[t] = g_ksum[t];
    __syncthreads();

    const int lane = t & 31;
    const int gw = (blockIdx.x * blockDim.x + t) >> 5;
    const int nw = (gridDim.x * blockDim.x) >> 5;
    for (int p = gw; p < NROWS / 2; p += nw) {
        const int r0 = p * 2, r1 = p * 2 + 1;
        const uint4 raw0 = *(const uint4*)&g_Q[r0 * DIM + lane * 8];
        const uint4 raw1 = *(const uint4*)&g_Q[r1 * DIM + lane * 8];
        const __half2* h0 = (const __half2*)&raw0;
        const __half2* h1 = (const __half2*)&raw1;
        float s0 = 0.0f, s1 = 0.0f;
#pragma unroll
        for (int i = 0; i < 4; i++) {
            const float k0 = ks[lane * 8 + i * 2], k1 = ks[lane * 8 + i * 2 + 1];
            float2 f0 = __half22float2(h0[i]);
            float2 f1 = __half22float2(h1[i]);
            s0 += f0.x * k0 + f0.y * k1;
            s1 += f1.x * k0 + f1.y * k1;
        }
#pragma unroll
        for (int o = 16; o; o >>= 1) {
            s0 += __shfl_xor_sync(0xffffffffu, s0, o);
            s1 += __shfl_xor_sync(0xffffffffu, s1, o);
        }
        if (lane == 0) { g_norm[r0] = s0 + EPS; g_norm[r1] = s1 + EPS; }
    }
}

// ---------------------------------------------------------------------------
// out: out = (Q @ KVh) * 256 / norm.  R9 shape, 4-stage single-barrier.
// grid (2, 782)
// ---------------------------------------------------------------------------
__global__ __launch_bounds__(256, 2) void out_kernel(float* __restrict__ out) {
    extern __shared__ char dsm[];

    const int t = threadIdx.x;
    const int l = t & 31, w = t >> 5;
    const int wm = w >> 1, wn = w & 1;

    const int col0 = blockIdx.x * 128;
    const int row0 = blockIdx.y * 128;

    const uint32_t as_base = smem_u32(dsm);
    const uint32_t bs_base = as_base + STAGES * ABYTES;
    const int aoff = (l & 15) * SA + (l >> 4) * 8;
    const int boff = ((l & 7) + ((l >> 3) & 1) * 8) * SB + (l >> 4) * 8;

    float c[2][8][4];
#pragma unroll
    for (int mt = 0; mt < 2; mt++)
#pragma unroll
        for (int nt = 0; nt < 8; nt++)
#pragma unroll
            for (int r = 0; r < 4; r++) c[mt][nt][r] = 0.0f;

    auto cp = [&](int kt) {
        const int s = kt % STAGES;
        const uint32_t da = as_base + s * ABYTES;
#pragma unroll
        for (int i = 0; i < 2; i++) {
            const int id = t + i * 256;
            const int row = id >> 2, cg = id & 3;
            cp16(da + (row * SA + cg * 8) * 2,
                 &g_Q[(row0 + row) * DIM + kt * 32 + cg * 8]);
        }
        const uint32_t db = bs_base + s * BBYTES;
#pragma unroll
        for (int i = 0; i < 2; i++) {
            const int id = t + i * 256;
            const int row = id >> 4, cg = id & 15;
            cp16(db + (row * SB + cg * 8) * 2,
                 &g_KVh[(kt * 32 + row) * DIM + col0 + cg * 8]);
        }
        CP_COMMIT();
    };
    auto compute = [&](int s) {
        const uint32_t ab = as_base + s * ABYTES;
        const uint32_t bb = bs_base + s * BBYTES;
#pragma unroll
        for (int ks = 0; ks < 2; ks++) {
            uint32_t a[2][4];
#pragma unroll
            for (int mt = 0; mt < 2; mt++)
                LDSM_X4(a[mt], ab + 2 * ((wm * 32 + mt * 16) * SA + ks * 16 + aoff));
            uint32_t b[4][4];
#pragma unroll
            for (int nt2 = 0; nt2 < 4; nt2++)
                LDSM_X4T(b[nt2], bb + 2 * (ks * 16 * SB + wn * 64 + nt2 * 16 + boff));
#pragma unroll
            for (int mt = 0; mt < 2; mt++)
#pragma unroll
                for (int nt = 0; nt < 8; nt++) {
                    const int nt2 = nt >> 1, i0 = (nt & 1) * 2;
                    mma_fp16(c[mt][nt], a[mt], b[nt2][i0], b[nt2][i0 + 1]);
                }
        }
    };

    cp(0); cp(1);
#pragma unroll 1
    for (int kt = 0; kt < 8; kt++) {
        if (kt + 2 < 8) cp(kt + 2);
        if (kt < 6) CP_WAIT(2); else if (kt == 6) CP_WAIT(1); else CP_WAIT(0);
        __syncthreads();
        compute(kt % STAGES);
    }

#pragma unroll
    for (int mt = 0; mt < 2; mt++) {
        const int gr0 = row0 + wm * 32 + mt * 16 + (l >> 2);
        const int gr1 = gr0 + 8;
        const float inv0 = (gr0 < NROWS) ? KV_SCALE_INV / g_norm[gr0] : 0.0f;
        const float inv1 = (gr1 < NROWS) ? KV_SCALE_INV / g_norm[gr1] : 0.0f;
#pragma unroll
        for (int nt = 0; nt < 8; nt++) {
            const int col = col0 + wn * 64 + nt * 8 + (l & 3) * 2;
            if (gr0 < NROWS)
                *(float2*)&out[gr0 * DIM + col] =
                    make_float2(c[mt][nt][0] * inv0, c[mt][nt][1] * inv0);
            if (gr1 < NROWS)
                *(float2*)&out[gr1 * DIM + col] =
                    make_float2(c[mt][nt][2] * inv1, c[mt][nt][3] * inv1);
        }
    }
}

// ---------------------------------------------------------------------------
extern "C" void kernel_launch(void* const* d_in, const int* in_sizes, int n_in,
                              void* d_out, int out_size) {
    const float* x  = (const float*)d_in[0];
    const float* Wq = (const float*)d_in[1];
    const float* bq = (const float*)d_in[2];
    const float* Wk = (const float*)d_in[3];
    const float* bk = (const float*)d_in[4];
    const float* Wv = (const float*)d_in[5];
    const float* bv = (const float*)d_in[6];
    float* out = (float*)d_out;

    cudaFuncSetAttribute(qkv_kernel, cudaFuncAttributeMaxDynamicSharedMemorySize, QKV_SMEM);
    cudaFuncSetAttribute(kv_kernel,  cudaFuncAttributeMaxDynamicSharedMemorySize, KV_SMEM);
    cudaFuncSetAttribute(out_kernel, cudaFuncAttributeMaxDynamicSharedMemorySize, OUT_SMEM);

    const int rowTiles = NPAD / 128;   // 782

    prep_kernel<<<12596, 256>>>(x, Wq, Wk, Wv);
    init_kernel<<<(DIM * DIM + 255) / 256, 256>>>();
    qkv_kernel<<<dim3(6, rowTiles), 256, QKV_SMEM>>>(bq, bk, bv);
    kv_kernel<<<dim3(4, KV_NCHUNK), 128, KV_SMEM>>>();
    norm_kernel<<<1184, 256>>>();
    out_kernel<<<dim3(2, rowTiles), 256, OUT_SMEM>>>(out);
}